// round 3
// baseline (speedup 1.0000x reference)
#include <cuda_runtime.h>

// ---------------- problem constants ----------------
#define NBLK 128
#define NTHR 256
#define LPn  128
#define LQn  128
#define Bn   64
#define Hn   150   // = D0

// ---------------- device scratch (static, allowed) ----------------
__device__ float d_wup[LPn * Bn * Hn];   // hoisted Up @ WpE^T
__device__ float d_Wuq[LQn * Bn * Hn];   // hoisted Uq @ WqE^T
__device__ float d_WgU[600 * 150];       // folded Wg (u part)
__device__ float d_WgC[600 * 150];       // folded Wg (c part)
__device__ float d_cc[Bn * 150];
__device__ float d_rg[Bn * 600];
__device__ float d_gh[Bn * 450];
__device__ float d_v[Bn * 150];
__device__ unsigned long long g_arrive;   // zero-init; monotonic across launches
__device__ unsigned long long g_release;

// ---------------- helpers ----------------
__device__ __forceinline__ float warp_sum(float v) {
#pragma unroll
    for (int o = 16; o > 0; o >>= 1) v += __shfl_down_sync(0xffffffffu, v, o);
    return v;
}
__device__ __forceinline__ float warp_max_all(float v) {
#pragma unroll
    for (int o = 16; o > 0; o >>= 1) v = fmaxf(v, __shfl_xor_sync(0xffffffffu, v, o));
    return v;
}
__device__ __forceinline__ float warp_sum_all(float v) {
#pragma unroll
    for (int o = 16; o > 0; o >>= 1) v += __shfl_xor_sync(0xffffffffu, v, o);
    return v;
}
__device__ __forceinline__ float fast_sig(float x) {
    return 1.0f / (1.0f + __expf(-x));
}
__device__ __forceinline__ float fast_tanh(float x) {
    float cx = fminf(fmaxf(x, -15.0f), 15.0f);
    float e  = __expf(2.0f * cx);
    return __fdividef(e - 1.0f, e + 1.0f);
}

// Grid barrier: monotonic counters (never reset -> robust across graph replays).
// All 128 blocks are co-resident (1-2 blocks/SM, grid < SM count) so no deadlock.
__device__ __forceinline__ void gsync(unsigned long long& gen) {
    __syncthreads();
    if (threadIdx.x == 0) {
        __threadfence();
        unsigned long long t = atomicAdd(&g_arrive, 1ULL);
        if (t == gen * (unsigned long long)NBLK + (NBLK - 1)) {
            atomicExch(&g_release, gen + 1ULL);
        } else {
            while (*((volatile unsigned long long*)&g_release) < gen + 1ULL) {
                __nanosleep(32);
            }
        }
        gen++;
        __threadfence();
    }
    __syncthreads();
}

// ---------------- the persistent kernel ----------------
__global__ void __launch_bounds__(NTHR, 1) pqm_kernel(
    const float* __restrict__ Up, const float* __restrict__ Uq,
    const float* __restrict__ Wp, const float* __restrict__ Wq,
    const float* __restrict__ Wv, const float* __restrict__ Wg,
    const float* __restrict__ Vmat, const float* __restrict__ v0,
    const float* __restrict__ W_ih, const float* __restrict__ W_hh,
    const float* __restrict__ b_ih, const float* __restrict__ b_hh,
    float* __restrict__ out)
{
    extern __shared__ float sm[];
    const int tid = threadIdx.x;
    const int blk = blockIdx.x;

    unsigned long long gen = 0;
    if (tid == 0) gen = *((volatile unsigned long long*)&g_release);

    // ======== P0: fold Wg into WgU/WgC; copy v0 -> v ========
    for (int idx = blk * NTHR + tid; idx < 600 * 150; idx += NBLK * NTHR) {
        int j = idx / 150, k = idx - j * 150;
        d_WgU[idx] = Wg[j * 600 + k]       + Wg[j * 600 + 150 + k];
        d_WgC[idx] = Wg[j * 600 + 300 + k] + Wg[j * 600 + 450 + k];
    }
    for (int idx = blk * NTHR + tid; idx < Bn * 150; idx += NBLK * NTHR)
        d_v[idx] = v0[idx];
    gsync(gen);

    // ======== P1: hoist wup = Up@WpE^T  and  Wuq = Uq@WqE^T (block = i / l) ========
    {
        float* we   = sm;              // 150*151 padded
        float* rowb = sm + 150 * 151;  // 150
        // --- Wp folded, staged in smem ---
        for (int idx = tid; idx < 150 * 150; idx += NTHR) {
            int h = idx / 150, d = idx - h * 150;
            we[h * 151 + d] = Wp[h * 300 + d] + Wp[h * 300 + 150 + d];
        }
        __syncthreads();
        for (int b = 0; b < Bn; b++) {
            if (tid < 150) rowb[tid] = Up[(blk * Bn + b) * 150 + tid];
            __syncthreads();
            if (tid < 150) {
                float acc = 0.f;
                const float* wr = &we[tid * 151];
#pragma unroll 5
                for (int d = 0; d < 150; d++) acc += rowb[d] * wr[d];
                d_wup[(blk * Bn + b) * 150 + tid] = acc;
            }
            __syncthreads();
        }
        // --- Wq folded ---
        for (int idx = tid; idx < 150 * 150; idx += NTHR) {
            int h = idx / 150, d = idx - h * 150;
            we[h * 151 + d] = Wq[h * 300 + d] + Wq[h * 300 + 150 + d];
        }
        __syncthreads();
        for (int b = 0; b < Bn; b++) {
            if (tid < 150) rowb[tid] = Uq[(blk * Bn + b) * 150 + tid];
            __syncthreads();
            if (tid < 150) {
                float acc = 0.f;
                const float* wr = &we[tid * 151];
#pragma unroll 5
                for (int d = 0; d < 150; d++) acc += rowb[d] * wr[d];
                d_Wuq[(blk * Bn + b) * 150 + tid] = acc;
            }
            __syncthreads();
        }
    }
    gsync(gen);

    // ======== main scan over LP steps ========
    for (int i = 0; i < LPn; i++) {
        // ---------- Phase A ----------
        if (blk < Bn) {
            // attention for batch row b = blk
            const int b  = blk;
            float* v_s  = sm;          // 150
            float* Vb   = sm + 152;    // 150
            float* bse  = sm + 304;    // 150
            float* sarr = sm + 456;    // 128
            if (tid < 150) {
                v_s[tid] = d_v[b * 150 + tid];
                Vb[tid]  = Vmat[b * 150 + tid];
            }
            __syncthreads();
            const int w = tid >> 5, ln = tid & 31;
            // base[h] = (v @ Wv^T)[h] + wup[i,b,h]   (warp per row)
            for (int it = 0; it < 19; it++) {
                int h = w + 8 * it;
                if (h < 150) {
                    float p = 0.f;
                    for (int k = ln; k < 150; k += 32) p += Wv[h * 150 + k] * v_s[k];
                    p = warp_sum(p);
                    if (ln == 0) bse[h] = p + d_wup[(i * Bn + b) * 150 + h];
                }
            }
            __syncthreads();
            // s[l] = sum_h tanh(base[h] + Wuq[l,b,h]) * V[b,h]   (warp per l)
            for (int it = 0; it < 16; it++) {
                int l = w + 8 * it;
                float p = 0.f;
                const float* wq = &d_Wuq[(l * Bn + b) * 150];
                for (int k = ln; k < 150; k += 32)
                    p += fast_tanh(bse[k] + wq[k]) * Vb[k];
                p = warp_sum(p);
                if (ln == 0) sarr[l] = p;
            }
            __syncthreads();
            // softmax over l (warp 0)
            if (w == 0) {
                float a0 = sarr[ln], a1 = sarr[ln + 32], a2 = sarr[ln + 64], a3 = sarr[ln + 96];
                float m = fmaxf(fmaxf(a0, a1), fmaxf(a2, a3));
                m = warp_max_all(m);
                float e0 = __expf(a0 - m), e1 = __expf(a1 - m);
                float e2 = __expf(a2 - m), e3 = __expf(a3 - m);
                float ssum = warp_sum_all(e0 + e1 + e2 + e3);
                float inv = __fdividef(1.0f, ssum);
                sarr[ln] = e0 * inv; sarr[ln + 32] = e1 * inv;
                sarr[ln + 64] = e2 * inv; sarr[ln + 96] = e3 * inv;
            }
            __syncthreads();
            // cc[d] = sum_l a[l] * Uq[l,b,d]
            if (tid < 150) {
                float acc = 0.f;
                for (int l = 0; l < LQn; l++)
                    acc += sarr[l] * Uq[(l * Bn + b) * 150 + tid];
                d_cc[b * 150 + tid] = acc;
            }
        } else {
            // gh = v @ W_hh^T + b_hh   (j-tile per block)
            const int bk = blk - Bn;
            float* v_sp = sm;  // 64*151
            for (int idx = tid; idx < Bn * 150; idx += NTHR) {
                int b = idx / 150, k = idx - b * 150;
                v_sp[b * 151 + k] = d_v[idx];
            }
            __syncthreads();
            int j0 = (bk * 450) >> 6, j1 = ((bk + 1) * 450) >> 6;
            int b = tid & 63, jg = tid >> 6;
            for (int j = j0 + jg; j < j1; j += 4) {
                float acc = b_hh[j];
                const float* wr = &W_hh[j * 150];
                const float* vr = &v_sp[b * 151];
#pragma unroll 5
                for (int k = 0; k < 150; k++) acc += vr[k] * wr[k];
                d_gh[b * 450 + j] = acc;
            }
        }
        gsync(gen);

        // ---------- Phase B: g = u@WgU^T + cc@WgC^T ; rg = sigmoid(g)*rbase ----------
        {
            float* u_s = sm;              // 64*151
            float* c_s = sm + Bn * 151;   // 64*151
            for (int idx = tid; idx < Bn * 150; idx += NTHR) {
                int b = idx / 150, k = idx - b * 150;
                u_s[b * 151 + k] = Up[i * Bn * 150 + idx];
                c_s[b * 151 + k] = d_cc[idx];
            }
            __syncthreads();
            int j0 = (blk * 600) >> 7, j1 = ((blk + 1) * 600) >> 7;
            int b = tid & 63, jg = tid >> 6;
            for (int j = j0 + jg; j < j1; j += 4) {
                float acc = 0.f;
                const float* wu = &d_WgU[j * 150];
                const float* wc = &d_WgC[j * 150];
                const float* ur = &u_s[b * 151];
                const float* cr = &c_s[b * 151];
#pragma unroll 5
                for (int k = 0; k < 150; k++) acc += ur[k] * wu[k] + cr[k] * wc[k];
                float sg = fast_sig(acc);
                int km = j % 150;
                float rb = (j < 300) ? ur[km] : cr[km];
                d_rg[b * 600 + j] = sg * rb;
            }
        }
        gsync(gen);

        // ---------- Phase C: gi = rg@W_ih^T + b_ih ; GRU combine ----------
        {
            const int half = blk & 1;     // which 32-batch half this block owns
            const int hb   = blk >> 1;    // base h task (0..63)
            const int b0   = half * 32;
            float* rg_s = sm;                 // 32*601
            float* sgv  = sm + 32 * 601;      // 2*96
            for (int idx = tid; idx < 32 * 600; idx += NTHR) {
                int b = idx / 600, k = idx - b * 600;
                rg_s[b * 601 + k] = d_rg[(b0 + b) * 600 + k];
            }
            __syncthreads();
            const int bloc = tid & 31;
            const int g    = (tid >> 5) % 3;      // only meaningful for tid<192
            const int grp  = tid / 96;            // 0 or 1 for tid<192
            for (int tb = 0; tb < 3; tb += 2) {
                int t = tb + grp;
                int h = hb + 64 * t;
                if (tid < 192 && h < 150) {
                    int j = g * 150 + h;
                    float acc = b_ih[j];
                    const float* wr = &W_ih[j * 600];
                    const float* rr = &rg_s[bloc * 601];
#pragma unroll 4
                    for (int k = 0; k < 600; k++) acc += rr[k] * wr[k];
                    sgv[grp * 96 + g * 32 + bloc] = acc;
                }
                __syncthreads();
                if (tid < 64) {
                    int grp2 = tid >> 5;
                    int bl   = tid & 31;
                    int h2   = hb + 64 * (tb + grp2);
                    if (h2 < 150) {
                        int b2 = b0 + bl;
                        float ir  = sgv[grp2 * 96 + bl];
                        float iz  = sgv[grp2 * 96 + 32 + bl];
                        float in_ = sgv[grp2 * 96 + 64 + bl];
                        float hr = d_gh[b2 * 450 + h2];
                        float hz = d_gh[b2 * 450 + 150 + h2];
                        float hn = d_gh[b2 * 450 + 300 + h2];
                        float r_ = fast_sig(ir + hr);
                        float z_ = fast_sig(iz + hz);
                        float n_ = fast_tanh(in_ + r_ * hn);
                        float vold = d_v[b2 * 150 + h2];
                        float hnew = (1.0f - z_) * n_ + z_ * vold;
                        d_v[b2 * 150 + h2] = hnew;
                        out[(i * Bn + b2) * 150 + h2] = hnew;
                    }
                }
                __syncthreads();
            }
        }
        gsync(gen);
    }
}

// ---------------- launch ----------------
#define SMEM_BYTES 92160   // max phase need: P1 (150*151+152)*4 = 91208 B

extern "C" void kernel_launch(void* const* d_in, const int* in_sizes, int n_in,
                              void* d_out, int out_size)
{
    const float* Up   = (const float*)d_in[0];
    const float* Uq   = (const float*)d_in[1];
    const float* Wp   = (const float*)d_in[2];
    const float* Wq   = (const float*)d_in[3];
    const float* Wv   = (const float*)d_in[4];
    const float* Wg   = (const float*)d_in[5];
    const float* Vm   = (const float*)d_in[6];
    const float* v0   = (const float*)d_in[7];
    const float* W_ih = (const float*)d_in[8];
    const float* W_hh = (const float*)d_in[9];
    const float* b_ih = (const float*)d_in[10];
    const float* b_hh = (const float*)d_in[11];
    float* out = (float*)d_out;

    cudaFuncSetAttribute(pqm_kernel, cudaFuncAttributeMaxDynamicSharedMemorySize, SMEM_BYTES);
    pqm_kernel<<<NBLK, NTHR, SMEM_BYTES>>>(Up, Uq, Wp, Wq, Wv, Wg, Vm, v0,
                                           W_ih, W_hh, b_ih, b_hh, out);
}

// round 4
// speedup vs baseline: 3.6830x; 3.6830x over previous
#include <cuda_runtime.h>

// ---------------- problem constants ----------------
#define NBLK 128
#define NTHR 256
#define LPn  128
#define LQn  128
#define Bn   64
#define Hn   150

// ---------------- device scratch ----------------
__device__ float d_wup[LPn * Bn * Hn];   // [i][b][h]
__device__ float d_Wuq[Bn * LQn * Hn];   // [b][l][h]  (relayout!)
__device__ float d_Uqt[Bn * LQn * Hn];   // [b][l][d]  (transposed Uq)
__device__ float d_WgU[600 * 150];
__device__ float d_WgC[600 * 150];
__device__ float d_cc[Bn * 150];
__device__ float d_rg[Bn * 600];
__device__ float d_gh[Bn * 450];
__device__ float d_v[Bn * 150];
__device__ unsigned long long g_arrive;
__device__ unsigned long long g_release;

// ---------------- smem layout (floats) ----------------
#define BUF_OFF   0
#define BUF_SZ    19712                 // scratch, aliased per phase
#define WGU_OFF   (BUF_OFF + BUF_SZ)    // 5*150
#define WGC_OFF   (WGU_OFF + 750)       // 5*150
#define WIH_OFF   (WGC_OFF + 750)       // 9*600
#define WHH_OFF   (WIH_OFF + 5400)      // 8*150
#define WV_OFF    (WHH_OFF + 1200)      // 150*151 (also P1 scratch)
#define SMEM_FL   (WV_OFF + 22650)      // 50462 floats
#define SMEM_BYTES (SMEM_FL * 4)        // 201848 B

// ---------------- helpers ----------------
__device__ __forceinline__ float warp_sum(float v) {
#pragma unroll
    for (int o = 16; o > 0; o >>= 1) v += __shfl_down_sync(0xffffffffu, v, o);
    return v;
}
__device__ __forceinline__ float warp_max_all(float v) {
#pragma unroll
    for (int o = 16; o > 0; o >>= 1) v = fmaxf(v, __shfl_xor_sync(0xffffffffu, v, o));
    return v;
}
__device__ __forceinline__ float warp_sum_all(float v) {
#pragma unroll
    for (int o = 16; o > 0; o >>= 1) v += __shfl_xor_sync(0xffffffffu, v, o);
    return v;
}
__device__ __forceinline__ float fast_sig(float x) {
    return 1.0f / (1.0f + __expf(-x));
}
__device__ __forceinline__ float fast_tanh(float x) {   // precise path (GRU)
    float cx = fminf(fmaxf(x, -15.0f), 15.0f);
    float e  = __expf(2.0f * cx);
    return __fdividef(e - 1.0f, e + 1.0f);
}
__device__ __forceinline__ float tanh_fastest(float x) { // attention path
    float y;
    asm("tanh.approx.f32 %0, %1;" : "=f"(y) : "f"(x));
    return y;
}

// Grid barrier: monotonic counters, robust across graph replays.
__device__ __forceinline__ void gsync(unsigned long long& gen) {
    __syncthreads();
    if (threadIdx.x == 0) {
        __threadfence();
        unsigned long long t = atomicAdd(&g_arrive, 1ULL);
        if (t == gen * (unsigned long long)NBLK + (NBLK - 1)) {
            atomicExch(&g_release, gen + 1ULL);
        } else {
            while (*((volatile unsigned long long*)&g_release) < gen + 1ULL) {
                __nanosleep(32);
            }
        }
        gen++;
        __threadfence();
    }
    __syncthreads();
}

// ---------------- the persistent kernel ----------------
__global__ void __launch_bounds__(NTHR, 1) pqm_kernel(
    const float* __restrict__ Up, const float* __restrict__ Uq,
    const float* __restrict__ Wp, const float* __restrict__ Wq,
    const float* __restrict__ Wv, const float* __restrict__ Wg,
    const float* __restrict__ Vmat, const float* __restrict__ v0,
    const float* __restrict__ W_ih, const float* __restrict__ W_hh,
    const float* __restrict__ b_ih, const float* __restrict__ b_hh,
    float* __restrict__ out)
{
    extern __shared__ float sm[];
    const int tid = threadIdx.x;
    const int blk = blockIdx.x;

    unsigned long long gen = 0;
    if (tid == 0) gen = *((volatile unsigned long long*)&g_release);

    // ======== P0: fold Wg; copy v0 ========
    for (int idx = blk * NTHR + tid; idx < 600 * 150; idx += NBLK * NTHR) {
        int j = idx / 150, k = idx - j * 150;
        d_WgU[idx] = Wg[j * 600 + k]       + Wg[j * 600 + 150 + k];
        d_WgC[idx] = Wg[j * 600 + 300 + k] + Wg[j * 600 + 450 + k];
    }
    for (int idx = blk * NTHR + tid; idx < Bn * 150; idx += NBLK * NTHR)
        d_v[idx] = v0[idx];
    gsync(gen);

    // ======== P1: hoist wup, Wuq (relayout), Uqt transpose ========
    {
        float* we   = sm + WV_OFF;     // 150*151 scratch (before Wv load)
        float* rowb = sm + BUF_OFF;    // 4*152
        const int m = blk;             // i index (for Up) / l index (for Uq)
        // --- Wp folded ---
        for (int idx = tid; idx < 150 * 150; idx += NTHR) {
            int h = idx / 150, d = idx - h * 150;
            we[h * 151 + d] = Wp[h * 300 + d] + Wp[h * 300 + 150 + d];
        }
        __syncthreads();
        for (int b0 = 0; b0 < Bn; b0 += 4) {
            for (int idx = tid; idx < 600; idx += NTHR) {
                int j = idx / 150, d = idx - j * 150;
                rowb[j * 152 + d] = Up[(m * Bn + b0 + j) * 150 + d];
            }
            __syncthreads();
            if (tid < 150) {
                float a0 = 0.f, a1 = 0.f, a2 = 0.f, a3 = 0.f;
                const float* wr = we + tid * 151;
#pragma unroll 6
                for (int k = 0; k < 150; k++) {
                    float w = wr[k];
                    a0 += w * rowb[k];       a1 += w * rowb[152 + k];
                    a2 += w * rowb[304 + k]; a3 += w * rowb[456 + k];
                }
                d_wup[(m * Bn + b0 + 0) * 150 + tid] = a0;
                d_wup[(m * Bn + b0 + 1) * 150 + tid] = a1;
                d_wup[(m * Bn + b0 + 2) * 150 + tid] = a2;
                d_wup[(m * Bn + b0 + 3) * 150 + tid] = a3;
            }
            __syncthreads();
        }
        // --- Wq folded ---
        for (int idx = tid; idx < 150 * 150; idx += NTHR) {
            int h = idx / 150, d = idx - h * 150;
            we[h * 151 + d] = Wq[h * 300 + d] + Wq[h * 300 + 150 + d];
        }
        __syncthreads();
        for (int b0 = 0; b0 < Bn; b0 += 4) {
            for (int idx = tid; idx < 600; idx += NTHR) {
                int j = idx / 150, d = idx - j * 150;
                float vv = Uq[(m * Bn + b0 + j) * 150 + d];
                rowb[j * 152 + d] = vv;
                d_Uqt[((b0 + j) * LQn + m) * 150 + d] = vv;   // transpose copy
            }
            __syncthreads();
            if (tid < 150) {
                float a0 = 0.f, a1 = 0.f, a2 = 0.f, a3 = 0.f;
                const float* wr = we + tid * 151;
#pragma unroll 6
                for (int k = 0; k < 150; k++) {
                    float w = wr[k];
                    a0 += w * rowb[k];       a1 += w * rowb[152 + k];
                    a2 += w * rowb[304 + k]; a3 += w * rowb[456 + k];
                }
                d_Wuq[((b0 + 0) * LQn + m) * 150 + tid] = a0;
                d_Wuq[((b0 + 1) * LQn + m) * 150 + tid] = a1;
                d_Wuq[((b0 + 2) * LQn + m) * 150 + tid] = a2;
                d_Wuq[((b0 + 3) * LQn + m) * 150 + tid] = a3;
            }
            __syncthreads();
        }
    }
    __syncthreads();

    // ======== load persistent weight slices into smem ========
    {
        // Phase B slice
        int j0b = (blk * 600) >> 7, nrb = (((blk + 1) * 600) >> 7) - j0b;
        for (int idx = tid; idx < nrb * 150; idx += NTHR) {
            int r = idx / 150, k = idx - r * 150;
            sm[WGU_OFF + idx] = d_WgU[(j0b + r) * 150 + k];
            sm[WGC_OFF + idx] = d_WgC[(j0b + r) * 150 + k];
        }
        // Phase C slice (row order o = t*3+g)
        int hb = blk >> 1;
        int nt = (hb < 22) ? 3 : 2;
        for (int idx = tid; idx < nt * 3 * 600; idx += NTHR) {
            int o = idx / 600, k = idx - o * 600;
            int t = o / 3, g = o - 3 * t;
            int j = g * 150 + hb + 64 * t;
            sm[WIH_OFF + idx] = W_ih[j * 600 + k];
        }
        if (blk >= Bn) {  // gh slice
            int bk = blk - Bn;
            int j0g = (bk * 450) >> 6, nrg = (((bk + 1) * 450) >> 6) - j0g;
            for (int idx = tid; idx < nrg * 150; idx += NTHR) {
                int r = idx / 150, k = idx - r * 150;
                sm[WHH_OFF + idx] = W_hh[(j0g + r) * 150 + k];
            }
        } else {          // full Wv, conflict-free stride 151
            for (int idx = tid; idx < 150 * 150; idx += NTHR) {
                int h = idx / 150, k = idx - h * 150;
                sm[WV_OFF + h * 151 + k] = Wv[h * 150 + k];
            }
        }
    }
    gsync(gen);

    const int w  = tid >> 5, ln = tid & 31;

    // ======== main scan ========
    for (int i = 0; i < LPn; i++) {
        // ---------- Phase A ----------
        if (blk < Bn) {
            const int b = blk;
            float* v_s  = sm + BUF_OFF;          // 150
            float* Vb   = sm + BUF_OFF + 152;    // 150
            float* bse  = sm + BUF_OFF + 304;    // 150
            float* a_s  = sm + BUF_OFF + 456;    // 128
            float* part = sm + BUF_OFF + 592;    // 8*152
            if (tid < 150) {
                v_s[tid] = d_v[b * 150 + tid];
                Vb[tid]  = Vmat[b * 150 + tid];
            }
            __syncthreads();
            // base[h] = wup + v@Wv^T  (smem dot, conflict-free)
            if (tid < 150) {
                float acc = d_wup[(i * Bn + b) * 150 + tid];
                const float* wr = sm + WV_OFF + tid * 151;
#pragma unroll 10
                for (int k = 0; k < 150; k++) acc += wr[k] * v_s[k];
                bse[tid] = acc;
            }
            __syncthreads();
            // s[l]: warp-per-l, coalesced Wuq rows
#pragma unroll 2
            for (int t = 0; t < 16; t++) {
                int l = w * 16 + t;
                const float* wq = &d_Wuq[(b * LQn + l) * 150];
                float p = 0.f;
#pragma unroll
                for (int k = ln; k < 150; k += 32)
                    p += tanh_fastest(bse[k] + wq[k]) * Vb[k];
                p = warp_sum(p);
                if (ln == 0) a_s[l] = p;
            }
            __syncthreads();
            // softmax (warp 0)
            if (w == 0) {
                float a0 = a_s[ln], a1 = a_s[ln + 32], a2 = a_s[ln + 64], a3 = a_s[ln + 96];
                float m = fmaxf(fmaxf(a0, a1), fmaxf(a2, a3));
                m = warp_max_all(m);
                float e0 = __expf(a0 - m), e1 = __expf(a1 - m);
                float e2 = __expf(a2 - m), e3 = __expf(a3 - m);
                float ssum = warp_sum_all(e0 + e1 + e2 + e3);
                float inv = __fdividef(1.0f, ssum);
                a_s[ln] = e0 * inv; a_s[ln + 32] = e1 * inv;
                a_s[ln + 64] = e2 * inv; a_s[ln + 96] = e3 * inv;
            }
            __syncthreads();
            // cc partials: warp w covers l in [16w,16w+16), lanes over d
#pragma unroll
            for (int p5 = 0; p5 < 5; p5++) {
                int d = ln + 32 * p5;
                if (d < 150) {
                    const float* uq = &d_Uqt[(b * LQn + w * 16) * 150 + d];
                    float acc = 0.f;
#pragma unroll
                    for (int t = 0; t < 16; t++)
                        acc += a_s[w * 16 + t] * uq[t * 150];
                    part[w * 152 + d] = acc;
                }
            }
            __syncthreads();
            if (tid < 150) {
                float acc = 0.f;
#pragma unroll
                for (int w2 = 0; w2 < 8; w2++) acc += part[w2 * 152 + tid];
                d_cc[b * 150 + tid] = acc;
            }
        } else {
            // gh = v @ W_hh^T + b_hh (smem weights)
            const int bk = blk - Bn;
            const int j0 = (bk * 450) >> 6, j1 = ((bk + 1) * 450) >> 6;
            float* v_sp = sm + BUF_OFF;   // 64*151
            for (int idx = tid; idx < Bn * 150; idx += NTHR) {
                int b = idx / 150, k = idx - b * 150;
                v_sp[b * 151 + k] = d_v[idx];
            }
            __syncthreads();
            int b = tid & 63, jg = tid >> 6;
            for (int j = j0 + jg; j < j1; j += 4) {
                int jl = j - j0;
                float acc = b_hh[j];
                const float* wr = sm + WHH_OFF + jl * 150;
                const float* vr = v_sp + b * 151;
#pragma unroll 10
                for (int k = 0; k < 150; k++) acc += vr[k] * wr[k];
                d_gh[b * 450 + j] = acc;
            }
        }
        gsync(gen);

        // ---------- Phase B ----------
        {
            float* u_s = sm + BUF_OFF;          // 64*151
            float* c_s = sm + BUF_OFF + 9664;   // 64*151
            const float* upi = Up + i * Bn * 150;
            for (int idx = tid; idx < Bn * 150; idx += NTHR) {
                int b = idx / 150, k = idx - b * 150;
                u_s[b * 151 + k] = upi[idx];
                c_s[b * 151 + k] = d_cc[idx];
            }
            __syncthreads();
            const int j0 = (blk * 600) >> 7, j1 = ((blk + 1) * 600) >> 7;
            int b = tid & 63, jg = tid >> 6;
            for (int j = j0 + jg; j < j1; j += 4) {
                int jl = j - j0;
                float acc = 0.f;
                const float* wu = sm + WGU_OFF + jl * 150;
                const float* wc = sm + WGC_OFF + jl * 150;
                const float* ur = u_s + b * 151;
                const float* cr = c_s + b * 151;
#pragma unroll 10
                for (int k = 0; k < 150; k++) acc += ur[k] * wu[k] + cr[k] * wc[k];
                float sg = fast_sig(acc);
                int km = j % 150;
                float rb = (j < 300) ? ur[km] : cr[km];
                d_rg[b * 600 + j] = sg * rb;
            }
        }
        gsync(gen);

        // ---------- Phase C ----------
        {
            const int half = blk & 1;
            const int hb   = blk >> 1;
            const int b0   = half * 32;
            const int nt   = (hb < 22) ? 3 : 2;
            const int no   = 3 * nt;
            float* rg_s = sm + BUF_OFF;             // 32 rows, stride 604 (151 f4)
            float* gi_s = sm + BUF_OFF + 19328;     // 9*32
            const float4* src = (const float4*)(d_rg + b0 * 600);
            float4* rg4 = (float4*)rg_s;
            for (int q = tid; q < 32 * 150; q += NTHR) {
                int bb = q / 150, kq = q - bb * 150;
                rg4[bb * 151 + kq] = src[bb * 150 + kq];
            }
            __syncthreads();
            const int bloc = tid & 31, og = tid >> 5;
            for (int o = og; o < no; o += 8) {
                int t = o / 3, g = o - 3 * t;
                int j = g * 150 + hb + 64 * t;
                float acc = b_ih[j];
                const float4* wr = (const float4*)(sm + WIH_OFF + o * 600);
                const float4* rr = rg4 + bloc * 151;
#pragma unroll 10
                for (int kq = 0; kq < 150; kq++) {
                    float4 a4 = rr[kq], w4 = wr[kq];
                    acc += a4.x * w4.x + a4.y * w4.y + a4.z * w4.z + a4.w * w4.w;
                }
                gi_s[o * 32 + bloc] = acc;
            }
            __syncthreads();
            if (tid < 96) {
                int t = tid >> 5, bl = tid & 31;
                if (t < nt) {
                    int h2 = hb + 64 * t;
                    int b2 = b0 + bl;
                    float ir  = gi_s[(t * 3 + 0) * 32 + bl];
                    float iz  = gi_s[(t * 3 + 1) * 32 + bl];
                    float in_ = gi_s[(t * 3 + 2) * 32 + bl];
                    float hr = d_gh[b2 * 450 + h2];
                    float hz = d_gh[b2 * 450 + 150 + h2];
                    float hn = d_gh[b2 * 450 + 300 + h2];
                    float r_ = fast_sig(ir + hr);
                    float z_ = fast_sig(iz + hz);
                    float n_ = fast_tanh(in_ + r_ * hn);
                    float vold = d_v[b2 * 150 + h2];
                    float hnew = (1.0f - z_) * n_ + z_ * vold;
                    d_v[b2 * 150 + h2] = hnew;
                    out[(i * Bn + b2) * 150 + h2] = hnew;
                }
            }
        }
        gsync(gen);
    }
}

// ---------------- launch ----------------
extern "C" void kernel_launch(void* const* d_in, const int* in_sizes, int n_in,
                              void* d_out, int out_size)
{
    const float* Up   = (const float*)d_in[0];
    const float* Uq   = (const float*)d_in[1];
    const float* Wp   = (const float*)d_in[2];
    const float* Wq   = (const float*)d_in[3];
    const float* Wv   = (const float*)d_in[4];
    const float* Wg   = (const float*)d_in[5];
    const float* Vm   = (const float*)d_in[6];
    const float* v0   = (const float*)d_in[7];
    const float* W_ih = (const float*)d_in[8];
    const float* W_hh = (const float*)d_in[9];
    const float* b_ih = (const float*)d_in[10];
    const float* b_hh = (const float*)d_in[11];
    float* out = (float*)d_out;

    cudaFuncSetAttribute(pqm_kernel, cudaFuncAttributeMaxDynamicSharedMemorySize, SMEM_BYTES);
    pqm_kernel<<<NBLK, NTHR, SMEM_BYTES>>>(Up, Uq, Wp, Wq, Wv, Wg, Vm, v0,
                                           W_ih, W_hh, b_ih, b_hh, out);
}